// round 7
// baseline (speedup 1.0000x reference)
#include <cuda_runtime.h>
#include <cuda_bf16.h>
#include <cstdint>

// ResiduePooling: scatter_mean(atom_features[2e6,128], residue_index(sorted) -> [250000,128])
//
// SINGLE fused kernel (no offsets array, no second launch):
//   - one warp owns 32 consecutive atoms; loads their indices coalesced,
//     detects segment starts via shfl_up + ballot.
//   - for each start in its range, the warp pools the ENTIRE segment
//     (probing past its range in 32-wide index chunks for the end; those
//     reads are the neighbor warp's lines -> L2 hits).
//   - empty residues zero-filled from the gap at each start (prev -> rs),
//     leading gap via prev=-1 at atom 0, trailing gap by the owner of the
//     last segment (send == n).
//   - lane owns one float4 of the 128-wide row; 512B coalesced LDG.128
//     streams with evict-streaming hints; one 512B row store per residue.
// Deterministic, atomic-free, every output row written exactly once.

#define NUM_RESIDUES 250000
#define FEAT_DIM 128

__device__ __forceinline__ bool detect_is64(const int* __restrict__ v, int n) {
    // Safe region: first n int32 slots exist for both dtypes.
    // int64 little-endian values < 2^31: every odd int32 slot is zero.
    int p0 = __ldg(v + 1);
    int p1 = __ldg(v + ((n > 1002) ? 1001 : 1));
    int p2 = __ldg(v + ((n > 100002) ? 100001 : 1));
    int p3 = __ldg(v + (n - 1));
    return ((p0 | p1 | p2 | p3) == 0);
}

__global__ void __launch_bounds__(64) fused_pool_kernel(const float* __restrict__ feat,
                                                        const void* __restrict__ idxv,
                                                        int n,
                                                        float* __restrict__ out) {
    const int gwarp = (blockIdx.x * blockDim.x + threadIdx.x) >> 5;
    const int lane  = threadIdx.x & 31;
    const int b     = gwarp * 32;
    if (b >= n) return;

    const bool is64 = detect_is64((const int*)idxv, n);
    const long long* __restrict__ p64 = (const long long*)idxv;
    const int* __restrict__       p32 = (const int*)idxv;

    // Load this warp's 32 indices (coalesced) + predecessor.
    int i = b + lane;
    bool valid = (i < n);
    int r = valid ? (is64 ? (int)p64[i] : p32[i]) : -2;
    int prev = __shfl_up_sync(0xffffffffu, r, 1);
    if (lane == 0) prev = (b == 0) ? -1 : (is64 ? (int)p64[b - 1] : p32[b - 1]);

    unsigned smask = __ballot_sync(0xffffffffu, valid && (r != prev));

    while (smask) {
        const int s = __ffs(smask) - 1;
        smask &= smask - 1;
        const int rs  = __shfl_sync(0xffffffffu, r, s);
        const int prs = __shfl_sync(0xffffffffu, prev, s);
        const int sstart = b + s;

        // Zero-fill empty residues in the gap (prs, rs).
        for (int q = prs + 1; q < rs; q++)
            __stcs((float4*)(out + (size_t)q * FEAT_DIM) + lane,
                   make_float4(0.f, 0.f, 0.f, 0.f));

        // Find segment end.
        int send;
        if (smask) {
            send = b + __ffs(smask) - 1;      // next start inside this warp's range
        } else {
            send = n;                         // default: runs to the end of data
            int off = b + 32;
            while (off < n) {
                int j = off + lane;
                int rr = (j < n) ? (is64 ? (int)p64[j] : p32[j]) : (rs + 1);
                unsigned ch = __ballot_sync(0xffffffffu, rr != rs);
                if (ch) { send = off + __ffs(ch) - 1; break; }
                off += 32;
            }
        }
        const bool last_seg = (send == n);

        // Pool [sstart, send): lane owns one float4 of the 128-wide row.
        int cnt = send - sstart;
        const float4* __restrict__ fp =
            (const float4*)(feat + (size_t)sstart * FEAT_DIM) + lane;

        float4 acc0 = make_float4(0.f, 0.f, 0.f, 0.f);
        float4 acc1 = make_float4(0.f, 0.f, 0.f, 0.f);

        int a = 0;
        for (; a + 4 <= cnt; a += 4) {
            float4 v0 = __ldcs(fp);
            float4 v1 = __ldcs(fp + 32);
            float4 v2 = __ldcs(fp + 64);
            float4 v3 = __ldcs(fp + 96);
            fp += 128;
            acc0.x += v0.x; acc0.y += v0.y; acc0.z += v0.z; acc0.w += v0.w;
            acc1.x += v1.x; acc1.y += v1.y; acc1.z += v1.z; acc1.w += v1.w;
            acc0.x += v2.x; acc0.y += v2.y; acc0.z += v2.z; acc0.w += v2.w;
            acc1.x += v3.x; acc1.y += v3.y; acc1.z += v3.z; acc1.w += v3.w;
        }
        if (a + 2 <= cnt) {
            float4 v0 = __ldcs(fp);
            float4 v1 = __ldcs(fp + 32);
            fp += 64;
            a += 2;
            acc0.x += v0.x; acc0.y += v0.y; acc0.z += v0.z; acc0.w += v0.w;
            acc1.x += v1.x; acc1.y += v1.y; acc1.z += v1.z; acc1.w += v1.w;
        }
        if (a < cnt) {
            float4 v0 = __ldcs(fp);
            acc0.x += v0.x; acc0.y += v0.y; acc0.z += v0.z; acc0.w += v0.w;
        }

        const float inv = 1.0f / (float)cnt;   // cnt >= 1 by construction
        float4 rw;
        rw.x = (acc0.x + acc1.x) * inv;
        rw.y = (acc0.y + acc1.y) * inv;
        rw.z = (acc0.z + acc1.z) * inv;
        rw.w = (acc0.w + acc1.w) * inv;
        __stcs((float4*)(out + (size_t)rs * FEAT_DIM) + lane, rw);

        // Trailing empty residues after the globally-last segment.
        if (last_seg) {
            for (int q = rs + 1; q < NUM_RESIDUES; q++)
                __stcs((float4*)(out + (size_t)q * FEAT_DIM) + lane,
                       make_float4(0.f, 0.f, 0.f, 0.f));
        }
    }
}

extern "C" void kernel_launch(void* const* d_in, const int* in_sizes, int n_in,
                              void* d_out, int out_size) {
    const float* feat = (const float*)d_in[0];
    const void* idx   = (const void*)d_in[1];
    int n_atoms       = in_sizes[1];

    // One warp per 32 atoms; 2 warps per 64-thread block.
    int total_warps = (n_atoms + 31) / 32;
    int blocks = (total_warps + 1) / 2;
    fused_pool_kernel<<<blocks, 64>>>(feat, idx, n_atoms, (float*)d_out);
}